// round 1
// baseline (speedup 1.0000x reference)
#include <cuda_runtime.h>
#include <cstdint>

#define N_NODES 100000
#define N_EDGES 1600000
#define IN_F    512
#define OUT_F   64

// Scratch (allocation-free rule: __device__ globals)
__device__ float g_h[(size_t)N_NODES * OUT_F];   // projected features, 25.6 MB
__device__ float g_deg[N_NODES];                 // in-degree per dst node

// ---------------------------------------------------------------------------
// 1) zero output accumulator + degree counters
// ---------------------------------------------------------------------------
__global__ void zero_kernel(float* __restrict__ out) {
    int i = blockIdx.x * blockDim.x + threadIdx.x;
    if (i < N_NODES * OUT_F) out[i] = 0.0f;
    if (i < N_NODES) g_deg[i] = 0.0f;
}

// ---------------------------------------------------------------------------
// 2) GEMM: g_h[100000,64] = feat[100000,512] @ W[512,64]
//    64x64 tile per block, BK=16, 256 threads, 4x4 register tile per thread.
// ---------------------------------------------------------------------------
__global__ __launch_bounds__(256) void gemm_kernel(
    const float* __restrict__ feat, const float* __restrict__ W)
{
    __shared__ float As[16][64];   // As[k][m]
    __shared__ float Bs[16][64];   // Bs[k][n]

    const int tid = threadIdx.x;
    const int m0  = blockIdx.x * 64;
    const int tx  = tid & 15;      // n-tile index
    const int ty  = tid >> 4;      // m-tile index

    // loader mapping for feat tile (64 rows x 16 k): float4 per thread
    const int lr = tid >> 2;            // row in tile, 0..63
    const int lc = (tid & 3) * 4;       // k offset, {0,4,8,12}
    // loader mapping for weight tile (16 k x 64 n): float4 per thread
    const int kw = tid >> 4;            // 0..15
    const int nw = (tid & 15) * 4;      // 0..60

    float acc[4][4] = {};

    for (int k0 = 0; k0 < IN_F; k0 += 16) {
        float4 fa = make_float4(0.f, 0.f, 0.f, 0.f);
        const int row = m0 + lr;
        if (row < N_NODES)
            fa = *reinterpret_cast<const float4*>(feat + (size_t)row * IN_F + k0 + lc);
        As[lc + 0][lr] = fa.x;
        As[lc + 1][lr] = fa.y;
        As[lc + 2][lr] = fa.z;
        As[lc + 3][lr] = fa.w;

        *reinterpret_cast<float4*>(&Bs[kw][nw]) =
            *reinterpret_cast<const float4*>(W + (size_t)(k0 + kw) * OUT_F + nw);

        __syncthreads();

        #pragma unroll
        for (int k = 0; k < 16; k++) {
            const float4 a = *reinterpret_cast<const float4*>(&As[k][ty * 4]);
            const float4 b = *reinterpret_cast<const float4*>(&Bs[k][tx * 4]);
            acc[0][0] += a.x * b.x; acc[0][1] += a.x * b.y; acc[0][2] += a.x * b.z; acc[0][3] += a.x * b.w;
            acc[1][0] += a.y * b.x; acc[1][1] += a.y * b.y; acc[1][2] += a.y * b.z; acc[1][3] += a.y * b.w;
            acc[2][0] += a.z * b.x; acc[2][1] += a.z * b.y; acc[2][2] += a.z * b.z; acc[2][3] += a.z * b.w;
            acc[3][0] += a.w * b.x; acc[3][1] += a.w * b.y; acc[3][2] += a.w * b.z; acc[3][3] += a.w * b.w;
        }
        __syncthreads();
    }

    const int row0 = m0 + ty * 4;
    #pragma unroll
    for (int i = 0; i < 4; i++) {
        const int r = row0 + i;
        if (r < N_NODES) {
            float4 v = make_float4(acc[i][0], acc[i][1], acc[i][2], acc[i][3]);
            *reinterpret_cast<float4*>(g_h + (size_t)r * OUT_F + tx * 4) = v;
        }
    }
}

// ---------------------------------------------------------------------------
// 3) Edge scatter: out[dst] += h[src] * w  via vector reductions (no return).
//    16 threads per edge, float4 each (64 floats). deg[dst] += 1 once/edge.
// ---------------------------------------------------------------------------
__global__ __launch_bounds__(256) void edge_kernel(
    const int* __restrict__ src, const int* __restrict__ dst,
    const float* __restrict__ ew, float* __restrict__ out)
{
    const long long t = (long long)blockIdx.x * blockDim.x + threadIdx.x;
    const int e = (int)(t >> 4);
    const int l = (int)(t & 15);
    if (e >= N_EDGES) return;

    const int s = __ldg(src + e);
    const int d = __ldg(dst + e);
    const float w = __ldg(ew + e);

    float4 v = *reinterpret_cast<const float4*>(g_h + (size_t)s * OUT_F + l * 4);
    v.x *= w; v.y *= w; v.z *= w; v.w *= w;

    float* p = out + (size_t)d * OUT_F + l * 4;
    asm volatile("red.global.add.v4.f32 [%0], {%1,%2,%3,%4};"
                 :: "l"(p), "f"(v.x), "f"(v.y), "f"(v.z), "f"(v.w)
                 : "memory");

    if (l == 0) atomicAdd(&g_deg[d], 1.0f);
}

// ---------------------------------------------------------------------------
// 4) finalize: out = relu( (deg>0 ? msum/deg : 0) + bias )
// ---------------------------------------------------------------------------
__global__ void finalize_kernel(float* __restrict__ out, const float* __restrict__ bias) {
    const int i = blockIdx.x * blockDim.x + threadIdx.x;
    if (i >= N_NODES * OUT_F) return;
    const int node = i >> 6;
    const int c    = i & 63;
    const float d = g_deg[node];
    float v = out[i];
    v = (d > 0.0f) ? (v / d) : 0.0f;
    v += __ldg(bias + c);
    out[i] = fmaxf(v, 0.0f);
}

// ---------------------------------------------------------------------------
extern "C" void kernel_launch(void* const* d_in, const int* in_sizes, int n_in,
                              void* d_out, int out_size)
{
    const float* feat     = (const float*)d_in[0];
    const float* edge_w   = (const float*)d_in[1];
    const float* weight   = (const float*)d_in[2];
    const float* bias     = (const float*)d_in[3];
    const int*   edge_src = (const int*)d_in[4];
    const int*   edge_dst = (const int*)d_in[5];
    float* out = (float*)d_out;

    zero_kernel<<<(N_NODES * OUT_F + 255) / 256, 256>>>(out);
    gemm_kernel<<<(N_NODES + 63) / 64, 256>>>(feat, weight);
    edge_kernel<<<(int)(((long long)N_EDGES * 16 + 255) / 256), 256>>>(edge_src, edge_dst, edge_w, out);
    finalize_kernel<<<(N_NODES * OUT_F + 255) / 256, 256>>>(out, bias);
}